// round 5
// baseline (speedup 1.0000x reference)
#include <cuda_runtime.h>
#include <cstdint>
#include <math_constants.h>

#define BB 2
#define SS 2048
#define DD 1024
#define HH 16
#define DKK 64
#define MTOT (BB * SS)   // 4096

// ---------------------------------------------------------------------------
// Scratch (device globals; no allocation allowed)
// ---------------------------------------------------------------------------
__device__ float g_Q[MTOT * DD];
__device__ float g_K[MTOT * DD];
__device__ float g_V[MTOT * DD];
__device__ float g_A[MTOT * DD];

// ---------------------------------------------------------------------------
// f32x2 packed-math helpers (base sm_100 ISA; PTX 8.6+)
// ---------------------------------------------------------------------------
__device__ __forceinline__ uint32_t smem_u32(const void* p) {
    uint32_t a;
    asm("{ .reg .u64 t; cvta.to.shared.u64 t, %1; cvt.u32.u64 %0, t; }" : "=r"(a) : "l"(p));
    return a;
}
__device__ __forceinline__ void fma2(uint64_t& d, uint64_t a, uint64_t b) {
    asm("fma.rn.f32x2 %0, %1, %2, %0;" : "+l"(d) : "l"(a), "l"(b));
}
__device__ __forceinline__ uint64_t add2(uint64_t a, uint64_t b) {
    uint64_t d; asm("add.rn.f32x2 %0, %1, %2;" : "=l"(d) : "l"(a), "l"(b)); return d;
}
__device__ __forceinline__ uint64_t mul2(uint64_t a, uint64_t b) {
    uint64_t d; asm("mul.rn.f32x2 %0, %1, %2;" : "=l"(d) : "l"(a), "l"(b)); return d;
}
__device__ __forceinline__ uint64_t pack2(float x, float y) {
    uint64_t d; asm("mov.b64 %0, {%1, %2};" : "=l"(d) : "f"(x), "f"(y)); return d;
}
__device__ __forceinline__ float2 unpack2(uint64_t v) {
    float2 r; asm("mov.b64 {%0, %1}, %2;" : "=f"(r.x), "=f"(r.y) : "l"(v)); return r;
}
__device__ __forceinline__ void lds2(uint64_t& a, uint64_t& b, uint32_t addr) {
    asm volatile("ld.shared.v2.u64 {%0, %1}, [%2];" : "=l"(a), "=l"(b) : "r"(addr));
}

// ---------------------------------------------------------------------------
// GEMM: C[M=4096, N=1024] = A @ W^T + bias, fp32 via packed f32x2.
// CTA 128x128, BK=16, 256 threads, 8x8 per-thread tile (as 8x4 f32x2 pairs).
// As: duplicated pairs (a,a) as u64, row stride APAD (2-way store conflicts ok).
// Bs: plain floats, row stride BPAD (16B-aligned for v2.u64 pair loads).
// ---------------------------------------------------------------------------
#define APAD 130   // u64 elements per As row
#define BPAD 132   // float elements per Bs row (132*4 = 528, 16B aligned)

__global__ __launch_bounds__(256, 2)
void gemm_f32x2(const float* __restrict__ A, const float* __restrict__ W,
                const float* __restrict__ bias, float* __restrict__ C)
{
    __shared__ uint64_t As[16][APAD];   // 16.6 KB
    __shared__ float    Bs[16][BPAD];   //  8.4 KB

    const int tid = threadIdx.x;
    const int tx = tid & 15;            // N direction
    const int ty = tid >> 4;            // M direction
    const int bm = blockIdx.y * 128;
    const int bn = blockIdx.x * 128;

    const uint32_t sAs = smem_u32(As);
    const uint32_t sBs = smem_u32(Bs);

    uint64_t acc[8][4];
#pragma unroll
    for (int i = 0; i < 8; i++)
#pragma unroll
        for (int j = 0; j < 4; j++) acc[i][j] = 0ull;

    for (int k0 = 0; k0 < DD; k0 += 16) {
#pragma unroll
        for (int it = 0; it < 2; it++) {
            int f = tid + it * 256;             // 0..511
            int row = f >> 2;                   // 0..127
            int kq = (f & 3) * 4;               // 0,4,8,12
            float4 va = *(const float4*)&A[(size_t)(bm + row) * DD + k0 + kq];
            float4 vb = *(const float4*)&W[(size_t)(bn + row) * DD + k0 + kq];
            float av[4] = {va.x, va.y, va.z, va.w};
            float bv[4] = {vb.x, vb.y, vb.z, vb.w};
#pragma unroll
            for (int j = 0; j < 4; j++) {
                uint32_t aaddr = sAs + (uint32_t)(((kq + j) * APAD + row) * 8);
                uint32_t au = __float_as_uint(av[j]);
                asm volatile("st.shared.v2.b32 [%0], {%1, %1};" :: "r"(aaddr), "r"(au));
                Bs[kq + j][row] = bv[j];
            }
        }
        __syncthreads();

#pragma unroll
        for (int kk = 0; kk < 16; kk++) {
            uint64_t a2[8], b2[4];
            uint32_t aa = sAs + (uint32_t)((kk * APAD + ty * 8) * 8);
            lds2(a2[0], a2[1], aa);
            lds2(a2[2], a2[3], aa + 16);
            lds2(a2[4], a2[5], aa + 32);
            lds2(a2[6], a2[7], aa + 48);
            uint32_t bb = sBs + (uint32_t)((kk * BPAD + tx * 8) * 4);
            lds2(b2[0], b2[1], bb);
            lds2(b2[2], b2[3], bb + 16);
#pragma unroll
            for (int i = 0; i < 8; i++)
#pragma unroll
                for (int j = 0; j < 4; j++)
                    fma2(acc[i][j], a2[i], b2[j]);
        }
        __syncthreads();
    }

    // Epilogue: packed bias add + 16B stores
    uint64_t bv2[4];
#pragma unroll
    for (int j = 0; j < 4; j++)
        bv2[j] = pack2(bias[bn + tx * 8 + 2 * j], bias[bn + tx * 8 + 2 * j + 1]);

#pragma unroll
    for (int i = 0; i < 8; i++) {
        uint64_t o0 = add2(acc[i][0], bv2[0]);
        uint64_t o1 = add2(acc[i][1], bv2[1]);
        uint64_t o2 = add2(acc[i][2], bv2[2]);
        uint64_t o3 = add2(acc[i][3], bv2[3]);
        size_t base = (size_t)(bm + ty * 8 + i) * DD + bn + tx * 8;
        *(ulonglong2*)&C[base]     = make_ulonglong2(o0, o1);
        *(ulonglong2*)&C[base + 4] = make_ulonglong2(o2, o3);
    }
}

// ---------------------------------------------------------------------------
// Causal flash attention, fp32 with f32x2, 4-way DK split.
// block 256: thread t -> query row (t>>2), quarter (t&3) of 16 dims.
// Scores reduced over the 4-lane group via shfl_xor(1),(2).
// ---------------------------------------------------------------------------
__global__ __launch_bounds__(256, 3)
void attn_causal(const float* __restrict__ Q, const float* __restrict__ K,
                 const float* __restrict__ V, float* __restrict__ O)
{
    __shared__ float Ks[64 * 64];
    __shared__ float Vs[64 * 64];
    __shared__ float Sc[64 * 64];

    const int qt = blockIdx.x;
    const int bh = blockIdx.y;
    const int b = bh >> 4;
    const int h = bh & 15;
    const int t = threadIdx.x;
    const int row = t >> 2;
    const int qu = t & 3;
    const int qg = qt * 64 + row;

    const uint32_t ksb = smem_u32(Ks);
    const uint32_t vsb = smem_u32(Vs);
    const uint32_t quoff = (uint32_t)(qu * 16 * 4);

    const float* qptr = Q + ((size_t)b * SS + qg) * DD + h * DKK + qu * 16;
    uint64_t q2[8];
    {
        const ulonglong2* qp = (const ulonglong2*)qptr;
#pragma unroll
        for (int j = 0; j < 4; j++) {
            ulonglong2 v = qp[j];
            q2[2 * j] = v.x; q2[2 * j + 1] = v.y;
        }
    }

    uint64_t a2[8];
#pragma unroll
    for (int i = 0; i < 8; i++) a2[i] = 0ull;

    float m = -CUDART_INF_F;
    float l = 0.f;

    for (int kt = 0; kt <= qt; kt++) {
        const float* kbase = K + ((size_t)b * SS + kt * 64) * DD + h * DKK;
        const float* vbase = V + ((size_t)b * SS + kt * 64) * DD + h * DKK;
#pragma unroll
        for (int i = 0; i < 4; i++) {
            int f = t + i * 256;
            int krow = f >> 4;
            int d4 = (f & 15) * 4;
            *(float4*)&Ks[krow * 64 + d4] = *(const float4*)(kbase + (size_t)krow * DD + d4);
            *(float4*)&Vs[krow * 64 + d4] = *(const float4*)(vbase + (size_t)krow * DD + d4);
        }
        __syncthreads();

        const bool diag = (kt == qt);
        float tmax = -CUDART_INF_F;
        for (int k = 0; k < 64; k++) {
            uint64_t kv[8];
            uint32_t ka = ksb + (uint32_t)(k * 256) + quoff;
            lds2(kv[0], kv[1], ka);
            lds2(kv[2], kv[3], ka + 16);
            lds2(kv[4], kv[5], ka + 32);
            lds2(kv[6], kv[7], ka + 48);
            uint64_t s2 = 0ull;
#pragma unroll
            for (int j = 0; j < 8; j++) fma2(s2, q2[j], kv[j]);
            float2 sp = unpack2(s2);
            float s = sp.x + sp.y;
            s += __shfl_xor_sync(0xffffffffu, s, 1);
            s += __shfl_xor_sync(0xffffffffu, s, 2);
            s *= 0.125f;                        // 1/sqrt(64)
            if (diag && k > row) s = -1e30f;
            if (qu == 0) Sc[k * 64 + row] = s;
            tmax = fmaxf(tmax, s);
        }

        const float m_new = fmaxf(m, tmax);
        const float alpha = __expf(m - m_new);
        l *= alpha;
        const uint64_t al2 = pack2(alpha, alpha);
#pragma unroll
        for (int i = 0; i < 8; i++) a2[i] = mul2(a2[i], al2);
        m = m_new;
        __syncwarp();

        for (int k = 0; k < 64; k++) {
            float p = __expf(Sc[k * 64 + row] - m);
            l += p;
            uint64_t vv[8];
            uint32_t va = vsb + (uint32_t)(k * 256) + quoff;
            lds2(vv[0], vv[1], va);
            lds2(vv[2], vv[3], va + 16);
            lds2(vv[4], vv[5], va + 32);
            lds2(vv[6], vv[7], va + 48);
            const uint64_t p2 = pack2(p, p);
#pragma unroll
            for (int i = 0; i < 8; i++) fma2(a2[i], p2, vv[i]);
        }
        __syncthreads();
    }

    const float inv = 1.f / l;
    const uint64_t i2 = pack2(inv, inv);
    float* optr = O + ((size_t)b * SS + qg) * DD + h * DKK + qu * 16;
    ulonglong2* op = (ulonglong2*)optr;
#pragma unroll
    for (int j = 0; j < 4; j++)
        op[j] = make_ulonglong2(mul2(a2[2 * j], i2), mul2(a2[2 * j + 1], i2));
}

// ---------------------------------------------------------------------------
// Launch. inputs: 0=query 1=key 2=value 3=mask 4=Wq 5=bq 6=Wk 7=bk 8=Wv 9=bv
//                 10=Wo 11=bo. mask is tril -> handled structurally.
// ---------------------------------------------------------------------------
extern "C" void kernel_launch(void* const* d_in, const int* in_sizes, int n_in,
                              void* d_out, int out_size)
{
    const float* query = (const float*)d_in[0];
    const float* key   = (const float*)d_in[1];
    const float* value = (const float*)d_in[2];
    const float* Wq = (const float*)d_in[4];
    const float* bq = (const float*)d_in[5];
    const float* Wk = (const float*)d_in[6];
    const float* bk = (const float*)d_in[7];
    const float* Wv = (const float*)d_in[8];
    const float* bv = (const float*)d_in[9];
    const float* Wo = (const float*)d_in[10];
    const float* bo = (const float*)d_in[11];
    float* out = (float*)d_out;

    float *gQ, *gK, *gV, *gA;
    cudaGetSymbolAddress((void**)&gQ, g_Q);
    cudaGetSymbolAddress((void**)&gK, g_K);
    cudaGetSymbolAddress((void**)&gV, g_V);
    cudaGetSymbolAddress((void**)&gA, g_A);

    dim3 ggrid(DD / 128, MTOT / 128);   // (8, 32)
    dim3 gblk(256);

    gemm_f32x2<<<ggrid, gblk>>>(query, Wq, bq, gQ);
    gemm_f32x2<<<ggrid, gblk>>>(key,   Wk, bk, gK);
    gemm_f32x2<<<ggrid, gblk>>>(value, Wv, bv, gV);

    dim3 agrid(SS / 64, BB * HH);       // (32, 32)
    attn_causal<<<agrid, 256>>>(gQ, gK, gV, gA);

    gemm_f32x2<<<ggrid, gblk>>>(gA, Wo, bo, out);
}

// round 6
// speedup vs baseline: 2.5562x; 2.5562x over previous
#include <cuda_runtime.h>
#include <cstdint>
#include <math_constants.h>

#define BB 2
#define SS 2048
#define DD 1024
#define HH 16
#define DKK 64
#define MTOT (BB * SS)   // 4096
#define NQT (SS / 64)    // 32 q-tiles per (b,h)

// ---------------------------------------------------------------------------
// Scratch (device globals; no allocation allowed)
// ---------------------------------------------------------------------------
__device__ float g_Q[MTOT * DD];
__device__ float g_K[MTOT * DD];
__device__ float g_V[MTOT * DD];
__device__ float g_A[MTOT * DD];

// ---------------------------------------------------------------------------
// GEMM: C[4096,1024] = A @ W^T + bias, fp32 scalar FFMA.
// CTA 128x128, BK=16, 256 threads, 8x8 per-thread tile in split 4+4 groups:
// rows {ty*4+i, 64+ty*4+i}, cols {tx*4+j, 64+tx*4+j}  -> conflict-free LDS.128.
// Staging transposed with row stride 132 floats (16B aligned, 2-way STS max).
// Register prefetch of next K-chunk hides global latency (single smem buffer).
// ---------------------------------------------------------------------------
#define SPAD 132

__global__ __launch_bounds__(256, 2)
void gemm_f32(const float* __restrict__ A, const float* __restrict__ W,
              const float* __restrict__ bias, float* __restrict__ C)
{
    __shared__ float As[16][SPAD];   // 8.45 KB
    __shared__ float Bs[16][SPAD];

    const int tid = threadIdx.x;
    const int tx = tid & 15;
    const int ty = tid >> 4;
    const int bm = blockIdx.y * 128;
    const int bn = blockIdx.x * 128;

    // staging coords (two 16B chunks per thread per array)
    const int f0 = tid;            // row f>>2, kq (f&3)*4
    const int f1 = tid + 256;
    const int r0 = f0 >> 2, k0q = (f0 & 3) * 4;
    const int r1 = f1 >> 2, k1q = (f1 & 3) * 4;

    const float* a0p = &A[(size_t)(bm + r0) * DD + k0q];
    const float* a1p = &A[(size_t)(bm + r1) * DD + k1q];
    const float* b0p = &W[(size_t)(bn + r0) * DD + k0q];
    const float* b1p = &W[(size_t)(bn + r1) * DD + k1q];

    float acc[8][8];
#pragma unroll
    for (int i = 0; i < 8; i++)
#pragma unroll
        for (int j = 0; j < 8; j++) acc[i][j] = 0.f;

    float4 pa0 = *(const float4*)a0p;
    float4 pa1 = *(const float4*)a1p;
    float4 pb0 = *(const float4*)b0p;
    float4 pb1 = *(const float4*)b1p;

    for (int c = 0; c < 64; c++) {
        // store staged chunk c
        {
            float av0[4] = {pa0.x, pa0.y, pa0.z, pa0.w};
            float av1[4] = {pa1.x, pa1.y, pa1.z, pa1.w};
            float bv0[4] = {pb0.x, pb0.y, pb0.z, pb0.w};
            float bv1[4] = {pb1.x, pb1.y, pb1.z, pb1.w};
#pragma unroll
            for (int j = 0; j < 4; j++) {
                As[k0q + j][r0] = av0[j];
                As[k1q + j][r1] = av1[j];
                Bs[k0q + j][r0] = bv0[j];
                Bs[k1q + j][r1] = bv1[j];
            }
        }
        __syncthreads();

        // prefetch chunk c+1
        if (c < 63) {
            const int off = (c + 1) * 16;
            pa0 = *(const float4*)(a0p + off);
            pa1 = *(const float4*)(a1p + off);
            pb0 = *(const float4*)(b0p + off);
            pb1 = *(const float4*)(b1p + off);
        }

#pragma unroll
        for (int kk = 0; kk < 16; kk++) {
            float4 aL = *(const float4*)&As[kk][ty * 4];
            float4 aH = *(const float4*)&As[kk][64 + ty * 4];
            float4 bL = *(const float4*)&Bs[kk][tx * 4];
            float4 bH = *(const float4*)&Bs[kk][64 + tx * 4];
            float a[8] = {aL.x, aL.y, aL.z, aL.w, aH.x, aH.y, aH.z, aH.w};
            float b[8] = {bL.x, bL.y, bL.z, bL.w, bH.x, bH.y, bH.z, bH.w};
#pragma unroll
            for (int i = 0; i < 8; i++)
#pragma unroll
                for (int j = 0; j < 8; j++)
                    acc[i][j] += a[i] * b[j];
        }
        __syncthreads();
    }

    // Epilogue: bias + 16B stores at split column groups
    float bL[4], bH[4];
#pragma unroll
    for (int j = 0; j < 4; j++) {
        bL[j] = bias[bn + tx * 4 + j];
        bH[j] = bias[bn + 64 + tx * 4 + j];
    }
#pragma unroll
    for (int ih = 0; ih < 2; ih++)
#pragma unroll
        for (int i = 0; i < 4; i++) {
            const int row = bm + ih * 64 + ty * 4 + i;
            float4 oL, oH;
            oL.x = acc[ih * 4 + i][0] + bL[0]; oL.y = acc[ih * 4 + i][1] + bL[1];
            oL.z = acc[ih * 4 + i][2] + bL[2]; oL.w = acc[ih * 4 + i][3] + bL[3];
            oH.x = acc[ih * 4 + i][4] + bH[0]; oH.y = acc[ih * 4 + i][5] + bH[1];
            oH.z = acc[ih * 4 + i][6] + bH[2]; oH.w = acc[ih * 4 + i][7] + bH[3];
            *(float4*)&C[(size_t)row * DD + bn + tx * 4] = oL;
            *(float4*)&C[(size_t)row * DD + bn + 64 + tx * 4] = oH;
        }
}

// ---------------------------------------------------------------------------
// Causal flash attention, fp32, thread = one query row (64 dims in regs).
// Work-balanced: block blockIdx.x = i handles q-tiles i and NQT-1-i
// -> exactly NQT+1 = 33 k-tiles per block, 512 uniform blocks (one wave @occ4).
// ---------------------------------------------------------------------------
__global__ __launch_bounds__(64, 4)
void attn_causal(const float* __restrict__ Q, const float* __restrict__ K,
                 const float* __restrict__ V, float* __restrict__ O)
{
    __shared__ float Ks[64 * 64];
    __shared__ float Vs[64 * 64];
    __shared__ float Sc[64 * 64];

    const int bh = blockIdx.y;
    const int b = bh >> 4;
    const int h = bh & 15;
    const int r = threadIdx.x;           // 0..63
    const float scale = 0.125f;          // 1/sqrt(64)

#pragma unroll 1
    for (int sel = 0; sel < 2; sel++) {
        const int qt = sel ? (NQT - 1 - blockIdx.x) : blockIdx.x;
        const int qg = qt * 64 + r;

        const float* qptr = Q + ((size_t)b * SS + qg) * DD + h * DKK;
        float4 q4[16];
#pragma unroll
        for (int i = 0; i < 16; i++) q4[i] = *(const float4*)&qptr[i * 4];

        float4 a4[16];
#pragma unroll
        for (int i = 0; i < 16; i++) a4[i] = make_float4(0.f, 0.f, 0.f, 0.f);

        float m = -CUDART_INF_F;
        float l = 0.f;

        for (int kt = 0; kt <= qt; kt++) {
            const float* kbase = K + ((size_t)b * SS + kt * 64) * DD + h * DKK;
            const float* vbase = V + ((size_t)b * SS + kt * 64) * DD + h * DKK;
#pragma unroll
            for (int i = 0; i < 16; i++) {
                int f = r + i * 64;
                int krow = f >> 4;
                int d4 = (f & 15) * 4;
                *(float4*)&Ks[krow * 64 + d4] = *(const float4*)&kbase[(size_t)krow * DD + d4];
                *(float4*)&Vs[krow * 64 + d4] = *(const float4*)&vbase[(size_t)krow * DD + d4];
            }
            __syncthreads();

            const int kmax = (kt < qt) ? 64 : (r + 1);

            // Pass 1: scores + tile max
            float tmax = -CUDART_INF_F;
            for (int k = 0; k < kmax; k++) {
                const float4* kk4 = (const float4*)&Ks[k * 64];
                float4 s4 = make_float4(0.f, 0.f, 0.f, 0.f);
#pragma unroll
                for (int i = 0; i < 16; i++) {
                    float4 kv = kk4[i];
                    s4.x += q4[i].x * kv.x; s4.y += q4[i].y * kv.y;
                    s4.z += q4[i].z * kv.z; s4.w += q4[i].w * kv.w;
                }
                float s = ((s4.x + s4.y) + (s4.z + s4.w)) * scale;
                Sc[k * 64 + r] = s;
                tmax = fmaxf(tmax, s);
            }

            const float m_new = fmaxf(m, tmax);
            const float alpha = __expf(m - m_new);
            l *= alpha;
#pragma unroll
            for (int i = 0; i < 16; i++) {
                a4[i].x *= alpha; a4[i].y *= alpha;
                a4[i].z *= alpha; a4[i].w *= alpha;
            }
            m = m_new;

            // Pass 2: p = exp(s - m), accumulate p * V
            for (int k = 0; k < kmax; k++) {
                float p = __expf(Sc[k * 64 + r] - m);
                l += p;
                const float4* vv4 = (const float4*)&Vs[k * 64];
#pragma unroll
                for (int i = 0; i < 16; i++) {
                    float4 vv = vv4[i];
                    a4[i].x += p * vv.x; a4[i].y += p * vv.y;
                    a4[i].z += p * vv.z; a4[i].w += p * vv.w;
                }
            }
            __syncthreads();
        }

        const float inv = 1.f / l;
        float* optr = O + ((size_t)b * SS + qg) * DD + h * DKK;
#pragma unroll
        for (int i = 0; i < 16; i++) {
            float4 o;
            o.x = a4[i].x * inv; o.y = a4[i].y * inv;
            o.z = a4[i].z * inv; o.w = a4[i].w * inv;
            *(float4*)&optr[i * 4] = o;
        }
    }
}

// ---------------------------------------------------------------------------
// Launch. inputs: 0=query 1=key 2=value 3=mask 4=Wq 5=bq 6=Wk 7=bk 8=Wv 9=bv
//                 10=Wo 11=bo. mask is tril -> handled structurally.
// ---------------------------------------------------------------------------
extern "C" void kernel_launch(void* const* d_in, const int* in_sizes, int n_in,
                              void* d_out, int out_size)
{
    const float* query = (const float*)d_in[0];
    const float* key   = (const float*)d_in[1];
    const float* value = (const float*)d_in[2];
    const float* Wq = (const float*)d_in[4];
    const float* bq = (const float*)d_in[5];
    const float* Wk = (const float*)d_in[6];
    const float* bk = (const float*)d_in[7];
    const float* Wv = (const float*)d_in[8];
    const float* bv = (const float*)d_in[9];
    const float* Wo = (const float*)d_in[10];
    const float* bo = (const float*)d_in[11];
    float* out = (float*)d_out;

    float *gQ, *gK, *gV, *gA;
    cudaGetSymbolAddress((void**)&gQ, g_Q);
    cudaGetSymbolAddress((void**)&gK, g_K);
    cudaGetSymbolAddress((void**)&gV, g_V);
    cudaGetSymbolAddress((void**)&gA, g_A);

    dim3 ggrid(DD / 128, MTOT / 128);   // (8, 32)
    dim3 gblk(256);

    gemm_f32<<<ggrid, gblk>>>(query, Wq, bq, gQ);
    gemm_f32<<<ggrid, gblk>>>(key,   Wk, bk, gK);
    gemm_f32<<<ggrid, gblk>>>(value, Wv, bv, gV);

    dim3 agrid(NQT / 2, BB * HH);       // (16, 32) balanced pairs
    attn_causal<<<agrid, 64>>>(gQ, gK, gV, gA);

    gemm_f32<<<ggrid, gblk>>>(gA, Wo, bo, out);
}